// round 5
// baseline (speedup 1.0000x reference)
#include <cuda_runtime.h>
#include <cstdint>

// Problem constants
#define LDX     1025          // x row length (1024 feats + 1 condition)
#define NDIM    1024
#define NBASIS  6

// Tiling
#define BM 128
#define BN 128
#define BK 32
#define NKC 192               // 32 d-chunks * 6 basis

#define PSTRIDE 20            // float2 per row (16 used + 4 pad -> conflict-free frag loads)
#define A_BYTES (128 * PSTRIDE * 8)      // 20480
#define B_BYTES (128 * PSTRIDE * 8)      // 20480 per stage
#define SMEM_DYN (A_BYTES + 2 * B_BYTES) // 61440

__device__ __forceinline__ uint32_t f2tf32(float f) {
    uint32_t u; asm("cvt.rna.tf32.f32 %0, %1;" : "=r"(u) : "f"(f)); return u;
}

__device__ __forceinline__ void mma_tf32(float* d, const uint32_t* a,
                                         uint32_t b0, uint32_t b1) {
    asm volatile(
        "mma.sync.aligned.m16n8k8.row.col.f32.tf32.tf32.f32 "
        "{%0,%1,%2,%3}, {%4,%5,%6,%7}, {%8,%9}, {%0,%1,%2,%3};"
        : "+f"(d[0]), "+f"(d[1]), "+f"(d[2]), "+f"(d[3])
        : "r"(a[0]), "r"(a[1]), "r"(a[2]), "r"(a[3]), "r"(b0), "r"(b1));
}

__global__ void __launch_bounds__(256, 1)
vclinear_mma(const float* __restrict__ x, const float* __restrict__ w,
             const float* __restrict__ bias, float* __restrict__ out)
{
    extern __shared__ char dsm[];
    float2* const apf = reinterpret_cast<float2*>(dsm);                 // A: raw fp32 pairs
    float2* const bpf0 = reinterpret_cast<float2*>(dsm + A_BYTES);      // B stage 0 (tf32)
    float2* const bpf1 = reinterpret_cast<float2*>(dsm + A_BYTES + B_BYTES);

    __shared__ float basis_s[BM * NBASIS];

    const int t    = threadIdx.x;
    const int wid  = t >> 5;
    const int lane = t & 31;
    const int g    = lane >> 2;          // group id (0..7)
    const int q4   = lane & 3;           // thread-in-group (0..3)
    const int wm   = (wid >> 1) * 32;    // warp M offset (4 warps in M)
    const int wn   = (wid & 1) * 64;     // warp N offset (2 warps in N)
    const int m0   = (blockIdx.x & 255) << 7;   // 256 M-tiles
    const int n0   = (blockIdx.x >> 8) << 7;    // 8 N-tiles; consecutive CTAs share n0

    // fill-role indices
    const int eB   = t & 127;            // B fill: output column within tile
    const int half = t >> 7;             // which 16 of the 32 k-values

    // basis per CTA row
    if (t < BM) {
        float tc = x[(size_t)(m0 + t) * LDX + NDIM];
        float* bs = &basis_s[t * NBASIS];
        bs[0] = 1.0f; bs[1] = tc; bs[2] = tc * tc;
        float r1 = fmaxf(tc - 0.25f, 0.0f);
        float r2 = fmaxf(tc - 0.50f, 0.0f);
        float r3 = fmaxf(tc - 0.75f, 0.0f);
        bs[3] = r1 * r1; bs[4] = r2 * r2; bs[5] = r3 * r3;
    }

    float acc[2][8][4];
    #pragma unroll
    for (int i = 0; i < 2; ++i)
        #pragma unroll
        for (int j = 0; j < 8; ++j)
            #pragma unroll
            for (int v = 0; v < 4; ++v) acc[i][j][v] = 0.0f;

    float vB[16], vA[16];

    // ---- fill helpers (inlined via lambdas) ----
    auto fillB = [&](int kc) {
        const int c  = kc % NBASIS;
        const int d0 = (kc / NBASIS) << 5;
        const float* wb = w + ((size_t)c << 20) + ((size_t)(d0 + (half << 4)) << 10) + n0 + eB;
        #pragma unroll
        for (int m = 0; m < 16; ++m) vB[m] = wb[(size_t)m << 10];
    };
    auto storeB = [&](float2* dst) {
        #pragma unroll
        for (int s2 = 0; s2 < 2; ++s2)
            #pragma unroll
            for (int q = 0; q < 4; ++q) {
                int sq = ((half << 1) + s2) * 4 + q;
                float2 v;
                v.x = __uint_as_float(f2tf32(vB[s2 * 8 + q]));
                v.y = __uint_as_float(f2tf32(vB[s2 * 8 + q + 4]));
                dst[eB * PSTRIDE + sq] = v;
            }
    };
    auto fillA = [&](int kc) {
        const int d0 = (kc / NBASIS) << 5;
        const float* xa = x + (size_t)(m0 + eB) * LDX + d0 + (half << 4);
        #pragma unroll
        for (int m = 0; m < 16; ++m) vA[m] = xa[m];
    };
    auto storeA = [&]() {
        #pragma unroll
        for (int s2 = 0; s2 < 2; ++s2)
            #pragma unroll
            for (int q = 0; q < 4; ++q) {
                int sq = ((half << 1) + s2) * 4 + q;
                apf[eB * PSTRIDE + sq] = make_float2(vA[s2 * 8 + q], vA[s2 * 8 + q + 4]);
            }
    };

    // ---- prologue: chunk 0 ----
    fillB(0); fillA(0);
    __syncthreads();            // basis_s + smem ready-to-write
    storeB(bpf0); storeA();
    __syncthreads();

    // ---- mainloop ----
    for (int kc = 0; kc < NKC; ++kc) {
        const int c = kc % NBASIS;
        float2* const bcur = (kc & 1) ? bpf1 : bpf0;
        float2* const bnext = (kc & 1) ? bpf0 : bpf1;
        const bool more  = (kc + 1) < NKC;
        const bool newA  = more && ((kc + 1) % NBASIS == 0);

        if (more) { fillB(kc + 1); if (newA) fillA(kc + 1); }   // LDGs fly under MMAs

        // per-chunk basis scalars
        float bs1[2], bs2[2];
        #pragma unroll
        for (int i = 0; i < 2; ++i) {
            bs1[i] = basis_s[(wm + i * 16 + g) * NBASIS + c];
            bs2[i] = basis_s[(wm + i * 16 + 8 + g) * NBASIS + c];
        }

        #pragma unroll
        for (int s = 0; s < 4; ++s) {
            uint32_t a[2][4];
            #pragma unroll
            for (int i = 0; i < 2; ++i) {
                float2 p0 = apf[(wm + i * 16 + g) * PSTRIDE + s * 4 + q4];
                float2 p1 = apf[(wm + i * 16 + 8 + g) * PSTRIDE + s * 4 + q4];
                a[i][0] = f2tf32(p0.x * bs1[i]);
                a[i][2] = f2tf32(p0.y * bs1[i]);
                a[i][1] = f2tf32(p1.x * bs2[i]);
                a[i][3] = f2tf32(p1.y * bs2[i]);
            }
            #pragma unroll
            for (int j = 0; j < 8; ++j) {
                float2 pb = bcur[(wn + j * 8 + g) * PSTRIDE + s * 4 + q4];
                uint32_t b0 = __float_as_uint(pb.x);
                uint32_t b1 = __float_as_uint(pb.y);
                mma_tf32(acc[0][j], a[0], b0, b1);
                mma_tf32(acc[1][j], a[1], b0, b1);
            }
        }

        if (more) {
            __syncthreads();                 // all warps done with bnext (chunk kc-1) & old A
            storeB(bnext); if (newA) storeA();
            __syncthreads();                 // next chunk visible
        }
    }

    // ---- epilogue: direct STG.64 with bias ----
    #pragma unroll
    for (int j = 0; j < 8; ++j) {
        const int col = n0 + wn + j * 8 + q4 * 2;
        const float2 bb = *reinterpret_cast<const float2*>(bias + col);
        #pragma unroll
        for (int i = 0; i < 2; ++i) {
            const int r1 = m0 + wm + i * 16 + g;
            float2 v1 = make_float2(acc[i][j][0] + bb.x, acc[i][j][1] + bb.y);
            float2 v2 = make_float2(acc[i][j][2] + bb.x, acc[i][j][3] + bb.y);
            *reinterpret_cast<float2*>(out + (size_t)r1 * NDIM + col) = v1;
            *reinterpret_cast<float2*>(out + (size_t)(r1 + 8) * NDIM + col) = v2;
        }
    }
}

// ---------------- launch ----------------
extern "C" void kernel_launch(void* const* d_in, const int* in_sizes, int n_in,
                              void* d_out, int out_size) {
    (void)in_sizes; (void)n_in; (void)out_size;
    const float* x    = (const float*)d_in[0];
    const float* w    = (const float*)d_in[1];
    const float* bias = (const float*)d_in[2];
    float* out = (float*)d_out;

    cudaFuncSetAttribute(vclinear_mma, cudaFuncAttributeMaxDynamicSharedMemorySize, SMEM_DYN);
    vclinear_mma<<<2048, 256, SMEM_DYN>>>(x, w, bias, out);
}

// round 6
// speedup vs baseline: 1.0663x; 1.0663x over previous
#include <cuda_runtime.h>
#include <cstdint>

// Problem constants
#define LDX     1025          // x row length (1024 feats + 1 condition)
#define NDIM    1024
#define NBASIS  6

// Tiling
#define BM 128
#define NKC 192               // 32 d-chunks * 6 basis

#define PSTRIDE 20            // float2 per row (16 used + 4 pad -> conflict-free frag loads)
#define A_BYTES (128 * PSTRIDE * 8)          // 20480
#define B_BYTES (128 * PSTRIDE * 8)          // 20480 per stage
#define SMEM_DYN (A_BYTES + 3 * B_BYTES)     // 81920: A + 3-stage B ring

__device__ __forceinline__ uint32_t f2tf32(float f) {
    uint32_t u; asm("cvt.rna.tf32.f32 %0, %1;" : "=r"(u) : "f"(f)); return u;
}

__device__ __forceinline__ void mma_tf32(float* d, const uint32_t* a,
                                         uint32_t b0, uint32_t b1) {
    asm volatile(
        "mma.sync.aligned.m16n8k8.row.col.f32.tf32.tf32.f32 "
        "{%0,%1,%2,%3}, {%4,%5,%6,%7}, {%8,%9}, {%0,%1,%2,%3};"
        : "+f"(d[0]), "+f"(d[1]), "+f"(d[2]), "+f"(d[3])
        : "r"(a[0]), "r"(a[1]), "r"(a[2]), "r"(a[3]), "r"(b0), "r"(b1));
}

__global__ void __launch_bounds__(256, 1)
vclinear_mma(const float* __restrict__ x, const float* __restrict__ w,
             const float* __restrict__ bias, float* __restrict__ out)
{
    extern __shared__ char dsm[];
    float2* const apf = reinterpret_cast<float2*>(dsm);              // A: raw fp32 pairs
    float2* bst[3];
    bst[0] = reinterpret_cast<float2*>(dsm + A_BYTES);
    bst[1] = reinterpret_cast<float2*>(dsm + A_BYTES + B_BYTES);
    bst[2] = reinterpret_cast<float2*>(dsm + A_BYTES + 2 * B_BYTES);

    __shared__ float basis_s[BM * NBASIS];

    const int t    = threadIdx.x;
    const int wid  = t >> 5;
    const int lane = t & 31;
    const int g    = lane >> 2;          // group id (0..7)
    const int q4   = lane & 3;           // thread-in-group (0..3)
    const int wm   = (wid >> 1) * 32;    // warp M offset (4 warps in M)
    const int wn   = (wid & 1) * 64;     // warp N offset (2 warps in N)
    const int m0   = (blockIdx.x & 255) << 7;   // 256 M-tiles
    const int n0   = (blockIdx.x >> 8) << 7;    // 8 N-tiles; consecutive CTAs share n0

    // fill-role indices
    const int eB   = t & 127;            // fill: row/col within tile
    const int half = t >> 7;             // which 16 of the 32 k-values

    // basis per CTA row
    if (t < BM) {
        float tc = x[(size_t)(m0 + t) * LDX + NDIM];
        float* bs = &basis_s[t * NBASIS];
        bs[0] = 1.0f; bs[1] = tc; bs[2] = tc * tc;
        float r1 = fmaxf(tc - 0.25f, 0.0f);
        float r2 = fmaxf(tc - 0.50f, 0.0f);
        float r3 = fmaxf(tc - 0.75f, 0.0f);
        bs[3] = r1 * r1; bs[4] = r2 * r2; bs[5] = r3 * r3;
    }

    float acc[2][8][4];
    #pragma unroll
    for (int i = 0; i < 2; ++i)
        #pragma unroll
        for (int j = 0; j < 8; ++j)
            #pragma unroll
            for (int v = 0; v < 4; ++v) acc[i][j][v] = 0.0f;

    // persistent raw A fragments for the current d-chunk:
    // araw[i][s][0] = feats pair (k=q4, k=q4+4) of row wm+i*16+g
    // araw[i][s][1] = same pair of row wm+i*16+8+g
    float2 araw[2][4][2];

    float vB[16], vA[16];

    // ---- fill helpers ----
    auto fillB = [&](int kc) {
        const int c  = kc % NBASIS;
        const int d0 = (kc / NBASIS) << 5;
        const float* wb = w + ((size_t)c << 20) + ((size_t)(d0 + (half << 4)) << 10) + n0 + eB;
        #pragma unroll
        for (int m = 0; m < 16; ++m) vB[m] = wb[(size_t)m << 10];
    };
    auto storeB = [&](float2* dst) {
        #pragma unroll
        for (int s2 = 0; s2 < 2; ++s2)
            #pragma unroll
            for (int q = 0; q < 4; ++q) {
                int sq = ((half << 1) + s2) * 4 + q;
                float2 v;
                v.x = __uint_as_float(f2tf32(vB[s2 * 8 + q]));
                v.y = __uint_as_float(f2tf32(vB[s2 * 8 + q + 4]));
                dst[eB * PSTRIDE + sq] = v;
            }
    };
    auto fillA = [&](int kc) {
        const int d0 = (kc / NBASIS) << 5;
        const float* xa = x + (size_t)(m0 + eB) * LDX + d0 + (half << 4);
        #pragma unroll
        for (int m = 0; m < 16; ++m) vA[m] = xa[m];
    };
    auto storeA = [&]() {
        #pragma unroll
        for (int s2 = 0; s2 < 2; ++s2)
            #pragma unroll
            for (int q = 0; q < 4; ++q) {
                int sq = ((half << 1) + s2) * 4 + q;
                apf[eB * PSTRIDE + sq] = make_float2(vA[s2 * 8 + q], vA[s2 * 8 + q + 4]);
            }
    };

    // ---- prologue: stage chunks 0,1 and d-chunk-0 feats ----
    fillB(0); fillA(0);
    storeB(bst[0]); storeA();
    fillB(1);
    __syncthreads();            // basis_s + bst[0] + A feats visible
    storeB(bst[1]);             // visible after chunk-0's end barrier, read at chunk 1

    // ---- mainloop: ONE barrier per chunk, 3-stage B ring, store-ahead-2 ----
    for (int kc = 0; kc < NKC; ++kc) {
        const int c = kc % NBASIS;

        // refresh persistent A fragments at each new d-chunk
        if (c == 0) {
            #pragma unroll
            for (int i = 0; i < 2; ++i)
                #pragma unroll
                for (int s = 0; s < 4; ++s) {
                    araw[i][s][0] = apf[(wm + i * 16 + g) * PSTRIDE + s * 4 + q4];
                    araw[i][s][1] = apf[(wm + i * 16 + 8 + g) * PSTRIDE + s * 4 + q4];
                }
        }

        // per-chunk basis scalars
        float bs1[2], bs2[2];
        #pragma unroll
        for (int i = 0; i < 2; ++i) {
            bs1[i] = basis_s[(wm + i * 16 + g) * NBASIS + c];
            bs2[i] = basis_s[(wm + i * 16 + 8 + g) * NBASIS + c];
        }

        // prefetch LDGs fly under the MMAs
        const bool pfB = (kc + 2) < NKC;
        if (pfB) fillB(kc + 2);
        if (c == 3 && (kc + 3) < NKC) fillA(kc + 3);

        float2* const bcur = bst[kc % 3];

        #pragma unroll
        for (int s = 0; s < 4; ++s) {
            uint32_t a[2][4];
            #pragma unroll
            for (int i = 0; i < 2; ++i) {
                a[i][0] = f2tf32(araw[i][s][0].x * bs1[i]);
                a[i][2] = f2tf32(araw[i][s][0].y * bs1[i]);
                a[i][1] = f2tf32(araw[i][s][1].x * bs2[i]);
                a[i][3] = f2tf32(araw[i][s][1].y * bs2[i]);
            }
            #pragma unroll
            for (int j = 0; j < 8; ++j) {
                float2 pb = bcur[(wn + j * 8 + g) * PSTRIDE + s * 4 + q4];
                uint32_t b0 = __float_as_uint(pb.x);
                uint32_t b1 = __float_as_uint(pb.y);
                mma_tf32(acc[0][j], a[0], b0, b1);
                mma_tf32(acc[1][j], a[1], b0, b1);
            }
        }

        // store-ahead-2: buffer (kc+2)%3 was last read at chunk kc-1 (>=1 barrier ago)
        if (pfB) storeB(bst[(kc + 2) % 3]);
        // next d-chunk feats: written here (kc%6==4), read at kc+2 (2 barriers later)
        if (c == 4 && (kc + 2) < NKC) storeA();

        __syncthreads();
    }

    // ---- epilogue: direct STG.64 with bias ----
    #pragma unroll
    for (int j = 0; j < 8; ++j) {
        const int col = n0 + wn + j * 8 + q4 * 2;
        const float2 bb = *reinterpret_cast<const float2*>(bias + col);
        #pragma unroll
        for (int i = 0; i < 2; ++i) {
            const int r1 = m0 + wm + i * 16 + g;
            float2 v1 = make_float2(acc[i][j][0] + bb.x, acc[i][j][1] + bb.y);
            float2 v2 = make_float2(acc[i][j][2] + bb.x, acc[i][j][3] + bb.y);
            *reinterpret_cast<float2*>(out + (size_t)r1 * NDIM + col) = v1;
            *reinterpret_cast<float2*>(out + (size_t)(r1 + 8) * NDIM + col) = v2;
        }
    }
}

// ---------------- launch ----------------
extern "C" void kernel_launch(void* const* d_in, const int* in_sizes, int n_in,
                              void* d_out, int out_size) {
    (void)in_sizes; (void)n_in; (void)out_size;
    const float* x    = (const float*)d_in[0];
    const float* w    = (const float*)d_in[1];
    const float* bias = (const float*)d_in[2];
    float* out = (float*)d_out;

    cudaFuncSetAttribute(vclinear_mma, cudaFuncAttributeMaxDynamicSharedMemorySize, SMEM_DYN);
    // 256 consecutive CTAs share an N-tile -> weight slice stays L2-hot
    vclinear_mma<<<2048, 256, SMEM_DYN>>>(x, w, bias, out);
}